// round 1
// baseline (speedup 1.0000x reference)
#include <cuda_runtime.h>
#include <cstdint>

#define B_ 1024
#define T_ 256
#define D_ 64
#define H_ 128

// Scratch for precomputed x-projections (pre-activation, bias included).
// g_xg[(b*T+t)*256 + j] = x[b,t] @ Wg[0:64, :] + bg   (gate: r cols 0..127, u cols 128..255)
// g_xc[(b*T+t)*128 + j] = x[b,t] @ Wc[0:64, :] + bc   (candidate)
__device__ float g_xg[(size_t)B_ * T_ * 256];
__device__ float g_xc[(size_t)B_ * T_ * 128];

// ---- packed f32x2 helpers (ptxas won't auto-fuse; must be PTX) ----
__device__ __forceinline__ unsigned long long pack2(float lo, float hi) {
    unsigned long long r;
    asm("mov.b64 %0, {%1, %2};" : "=l"(r) : "f"(lo), "f"(hi));
    return r;
}
__device__ __forceinline__ void fma2(unsigned long long& acc,
                                     unsigned long long a,
                                     unsigned long long b) {
    asm("fma.rn.f32x2 %0, %1, %2, %0;" : "+l"(acc) : "l"(a), "l"(b));
}
__device__ __forceinline__ float sum2(unsigned long long a) {
    float lo, hi;
    asm("mov.b64 {%0, %1}, %2;" : "=f"(lo), "=f"(hi) : "l"(a));
    return lo + hi;
}

// ============================================================================
// Phase A: time-parallel x-projections.
// Grid (4 t-tiles of 64, B rows). 384 threads: tid<256 -> gate col, else cand col.
// Weight column cached in registers (packed pairs along k); x tile gathered to SMEM.
// ============================================================================
__global__ __launch_bounds__(384)
void gru_phaseA(const int* __restrict__ item_his,
                const int* __restrict__ seq_lens,
                const float* __restrict__ emb,
                const float* __restrict__ Wg,
                const float* __restrict__ bg,
                const float* __restrict__ Wc,
                const float* __restrict__ bc)
{
    const int b  = blockIdx.y;
    const int t0 = blockIdx.x * 64;
    const int len = seq_lens[b];
    if (t0 >= len) return;                 // steps >= seq_len are never read
    const int nt = min(64, len - t0);
    const int tid = threadIdx.x;

    __shared__ int   idx_sh[64];
    __shared__ float x_sh[64 * 64];        // [row][k], rows read via broadcast

    // Cache this thread's weight column (k = 0..63) as 32 packed pairs.
    unsigned long long wp[32];
    float bias;
    if (tid < 256) {
        bias = bg[tid];
#pragma unroll
        for (int i = 0; i < 32; i++)
            wp[i] = pack2(Wg[(2 * i) * 256 + tid], Wg[(2 * i + 1) * 256 + tid]);
    } else {
        const int c = tid - 256;
        bias = bc[c];
#pragma unroll
        for (int i = 0; i < 32; i++)
            wp[i] = pack2(Wc[(2 * i) * 128 + c], Wc[(2 * i + 1) * 128 + c]);
    }

    if (tid < nt) idx_sh[tid] = item_his[b * T_ + t0 + tid];
    __syncthreads();

    {   // coalesced gather: 64 embedding rows of 256B each
        const float4* e4 = (const float4*)emb;
        float4* x4 = (float4*)x_sh;
        for (int i = tid; i < nt * 16; i += 384) {
            const int r = i >> 4, q = i & 15;
            x4[r * 16 + q] = e4[(size_t)idx_sh[r] * 16 + q];
        }
    }
    __syncthreads();

    const unsigned long long* x2 = (const unsigned long long*)x_sh;
    for (int r = 0; r < nt; r++) {
        unsigned long long a0 = 0ULL, a1 = 0ULL;   // (0.f,0.f)
#pragma unroll
        for (int i = 0; i < 32; i += 2) {
            fma2(a0, x2[r * 32 + i],     wp[i]);
            fma2(a1, x2[r * 32 + i + 1], wp[i + 1]);
        }
        const float acc = sum2(a0) + sum2(a1) + bias;
        const size_t p = (size_t)b * T_ + t0 + r;
        if (tid < 256) g_xg[p * 256 + tid] = acc;          // coalesced
        else           g_xc[p * 128 + (tid - 256)] = acc;  // coalesced
    }
}

// ============================================================================
// Phase B: sequential recurrence, one CTA per batch row (independent rows,
// no global sync). Recurrent weights register-resident (64 packed b64 regs),
// h broadcast from SMEM, f32x2 FMA. Next-step x-projection prefetched.
// ============================================================================
__global__ __launch_bounds__(384, 1)
void gru_phaseB(const int* __restrict__ seq_lens,
                const float* __restrict__ Wg,
                const float* __restrict__ Wc,
                float* __restrict__ out)
{
    const int b   = blockIdx.x;
    const int len = seq_lens[b];
    const int tid = threadIdx.x;

    __shared__ float h_sh[128];
    __shared__ float rh_sh[128];
    __shared__ float u_sh[128];

    if (tid < 128) h_sh[tid] = 0.f;

    // Recurrent weight column (k = 0..127) as 64 packed pairs, in registers.
    unsigned long long wp[64];
    if (tid < 256) {
#pragma unroll
        for (int i = 0; i < 64; i++)
            wp[i] = pack2(Wg[(64 + 2 * i) * 256 + tid],
                          Wg[(64 + 2 * i + 1) * 256 + tid]);
    } else {
        const int c = tid - 256;
#pragma unroll
        for (int i = 0; i < 64; i++)
            wp[i] = pack2(Wc[(64 + 2 * i) * 128 + c],
                          Wc[(64 + 2 * i + 1) * 128 + c]);
    }
    __syncthreads();

    const unsigned long long* h2  = (const unsigned long long*)h_sh;
    const unsigned long long* rh2 = (const unsigned long long*)rh_sh;

    float xv = 0.f;
    if (len > 0)
        xv = (tid < 256) ? g_xg[((size_t)b * T_) * 256 + tid]
                         : g_xc[((size_t)b * T_) * 128 + (tid - 256)];

    for (int t = 0; t < len; t++) {
        // prefetch next step's x-projection (consumed next iteration)
        float xvn = 0.f;
        if (t + 1 < len)
            xvn = (tid < 256)
                ? g_xg[((size_t)b * T_ + t + 1) * 256 + tid]
                : g_xc[((size_t)b * T_ + t + 1) * 128 + (tid - 256)];

        // --- gates: tid<256 owns one gate column ---
        if (tid < 256) {
            unsigned long long a0 = 0ULL, a1 = 0ULL, a2 = 0ULL, a3 = 0ULL;
#pragma unroll
            for (int i = 0; i < 64; i += 4) {
                fma2(a0, h2[i],     wp[i]);
                fma2(a1, h2[i + 1], wp[i + 1]);
                fma2(a2, h2[i + 2], wp[i + 2]);
                fma2(a3, h2[i + 3], wp[i + 3]);
            }
            const float s = sum2(a0) + sum2(a1) + sum2(a2) + sum2(a3) + xv;
            const float g = 1.f / (1.f + __expf(-s));
            if (tid < 128) rh_sh[tid] = g * h_sh[tid];   // r * h
            else           u_sh[tid - 128] = g;          // u
        }
        __syncthreads();

        // --- candidate + state update: tid in [256,384) owns one h column ---
        float hn = 0.f;
        if (tid >= 256) {
            const int j = tid - 256;
            unsigned long long a0 = 0ULL, a1 = 0ULL, a2 = 0ULL, a3 = 0ULL;
#pragma unroll
            for (int i = 0; i < 64; i += 4) {
                fma2(a0, rh2[i],     wp[i]);
                fma2(a1, rh2[i + 1], wp[i + 1]);
                fma2(a2, rh2[i + 2], wp[i + 2]);
                fma2(a3, rh2[i + 3], wp[i + 3]);
            }
            const float s  = sum2(a0) + sum2(a1) + sum2(a2) + sum2(a3) + xv;
            const float sc = fminf(fmaxf(s, -15.f), 15.f);
            const float e  = __expf(2.f * sc);
            const float c  = (e - 1.f) / (e + 1.f);     // tanh, overflow-safe
            const float u  = u_sh[j];
            hn = u * h_sh[j] + (1.f - u) * c;
        }
        __syncthreads();
        if (tid >= 256) h_sh[tid - 256] = hn;
        __syncthreads();

        xv = xvn;
    }

    if (tid < 128) out[b * H_ + tid] = h_sh[tid];
}

// ============================================================================
extern "C" void kernel_launch(void* const* d_in, const int* in_sizes, int n_in,
                              void* d_out, int out_size)
{
    const int*   item_his = (const int*)d_in[0];
    const int*   seq_lens = (const int*)d_in[1];
    const float* emb      = (const float*)d_in[2];
    const float* Wg       = (const float*)d_in[3];
    const float* bg       = (const float*)d_in[4];
    const float* Wc       = (const float*)d_in[5];
    const float* bc       = (const float*)d_in[6];
    float* out = (float*)d_out;

    dim3 gA(T_ / 64, B_);   // (4, 1024)
    gru_phaseA<<<gA, 384>>>(item_his, seq_lens, emb, Wg, bg, Wc, bc);
    gru_phaseB<<<B_, 384>>>(seq_lens, Wg, Wc, out);
}